// round 15
// baseline (speedup 1.0000x reference)
#include <cuda_runtime.h>
#include <cstdint>

// Problem constants: B=512, T=256, C=384, HS=16
#define TT   256
#define CC   384
#define HSZ  16
#define KCH  16          // K-chunk for projection (k16 granularity)
#define NKC  (CC/KCH)    // 24
#define XP   24          // x tile row stride (floats): grp*24 mod 32 = {0,24,16,8} -> conflict-free LDS.64

// packed W: 24 k16-chunks x 48 cb x 4 tig, uint4 = {bh0, bh1, bl0, bl1}
__device__ uint4 g_w4[24 * 192];

// smem (floats):
//  phase1 (max): x 2*256*24 = 12288 + W4 2*192*4 = 1536 -> 13824 f = 55296 B
//  phase2: q_pk 4096 + k_pk 4096 + v_pk 4096 + psum 512 = 12800 f = 51200 B
#define SMEM_FLOATS (2 * TT * XP + 2 * 192 * 4)
#define SMEM_BYTES  (SMEM_FLOATS * 4)

__device__ __forceinline__ unsigned f2tf(float f) {
    unsigned r;
    asm("cvt.rna.tf32.f32 %0, %1;" : "=r"(r) : "f"(f));
    return r;
}
__device__ __forceinline__ unsigned pk2(float lo, float hi) {
    unsigned r;
    asm("cvt.rn.bf16x2.f32 %0, %1, %2;" : "=r"(r) : "f"(hi), "f"(lo));
    return r;
}
__device__ __forceinline__ float bflo(unsigned u) { return __uint_as_float(u << 16); }
__device__ __forceinline__ float bfhi(unsigned u) { return __uint_as_float(u & 0xffff0000u); }
__device__ __forceinline__ unsigned pkres(float lo, float hi, unsigned h) {
    return pk2(lo - bflo(h), hi - bfhi(h));
}

__device__ __forceinline__ void mma_tf32(float* c, const unsigned* a, const unsigned* b) {
    asm volatile(
        "mma.sync.aligned.m16n8k8.row.col.f32.tf32.tf32.f32 "
        "{%0,%1,%2,%3}, {%4,%5,%6,%7}, {%8,%9}, {%0,%1,%2,%3};"
        : "+f"(c[0]), "+f"(c[1]), "+f"(c[2]), "+f"(c[3])
        : "r"(a[0]), "r"(a[1]), "r"(a[2]), "r"(a[3]), "r"(b[0]), "r"(b[1]));
}
__device__ __forceinline__ void mma_bf16(float* c, const unsigned* a, const unsigned* b) {
    asm volatile(
        "mma.sync.aligned.m16n8k16.row.col.f32.bf16.bf16.f32 "
        "{%0,%1,%2,%3}, {%4,%5,%6,%7}, {%8,%9}, {%0,%1,%2,%3};"
        : "+f"(c[0]), "+f"(c[1]), "+f"(c[2]), "+f"(c[3])
        : "r"(a[0]), "r"(a[1]), "r"(a[2]), "r"(a[3]), "r"(b[0]), "r"(b[1]));
}
__device__ __forceinline__ void cpa16(uint32_t saddr, const void* g) {
    asm volatile("cp.async.ca.shared.global [%0], [%1], 16;" :: "r"(saddr), "l"(g));
}

// ===== pre-kernel: pack W into B-fragment uint4 layout (q-cols pre-scaled) =======
__global__ void pack_w_kernel(const float* __restrict__ wk,
                              const float* __restrict__ wq,
                              const float* __restrict__ wv)
{
    int f = blockIdx.x * 256 + threadIdx.x;      // 0..4607
    if (f >= 24 * 192) return;
    int chunk = f / 192;
    int rem   = f % 192;
    int cb    = rem / 4;
    int tg    = rem % 4;

    const float* w;
    int c;
    float s = 1.0f;
    if (cb < 16)      { w = wq; c = cb;      s = rsqrtf((float)CC); }
    else if (cb < 32) { w = wk; c = cb - 16; }
    else              { w = wv; c = cb - 32; }

    int kA = chunk * 16 + 2 * tg;
    int kB = kA + 8;
    float a0 = w[kA * HSZ + c] * s;
    float a1 = w[(kA + 1) * HSZ + c] * s;
    float b0 = w[kB * HSZ + c] * s;
    float b1 = w[(kB + 1) * HSZ + c] * s;
    unsigned h0 = pk2(a0, a1);
    unsigned h1 = pk2(b0, b1);
    uint4 r;
    r.x = h0;
    r.y = h1;
    r.z = pkres(a0, a1, h0);
    r.w = pkres(b0, b1, h1);
    g_w4[f] = r;
}

// ====================== fused kernel: projection + attention ======================
__global__ void __launch_bounds__(256, 3) head_fused_kernel(
    const float* __restrict__ x,
    float* __restrict__ out)
{
    extern __shared__ float sm[];
    const int b    = blockIdx.x;
    const int tid  = threadIdx.x;
    const int lane = tid & 31;
    const int warp = tid >> 5;
    const int grp  = lane >> 2;  // 0..7
    const int tig  = lane & 3;   // 0..3

    const uint32_t sm_base = (uint32_t)__cvta_generic_to_shared(sm);

    // phase-2 smem views (fragment-packed; overlap phase-1 region)
    float* q_pk = sm;             // [16 strips][2 k8][32 lanes] float4
    float* k_pk = sm + 4096;      // [8 blk][2 k8][2 ntpair][32 lanes] float4
    float* v_pk = sm + 8192;      // [8 blk][2 ch][2 nt][32 lanes] float4
    float* psum = sm + 12288;     // [2][256] parity-buffered

    const float* xb = x + (size_t)b * TT * CC;
    const int R = warp * 32;

    // ======= Phase 1: qkv = x @ Wpacked, bf16 3-term, one barrier per chunk ======
    float acc[2][6][4];
#pragma unroll
    for (int mt = 0; mt < 2; ++mt)
#pragma unroll
        for (int nt = 0; nt < 6; ++nt)
#pragma unroll
            for (int e = 0; e < 4; ++e) acc[mt][nt][e] = 0.f;

    const uint32_t wsm_off = (uint32_t)(2 * TT * XP) * 4u;   // byte offset of W4 region

    auto load_chunk = [&](int kc, int buf) {
        const float* xg = xb + kc * KCH;
        uint32_t xs_a = sm_base + (uint32_t)(buf * TT * XP) * 4u;
#pragma unroll
        for (int i = 0; i < 4; ++i) {
            int row = (tid >> 2) + i * 64;
            int c4  = (tid & 3) * 4;
            cpa16(xs_a + (uint32_t)(row * XP + c4) * 4u, xg + row * CC + c4);
        }
        if (tid < 192) {
            const uint4* srcW = g_w4 + kc * 192 + tid;
            uint32_t wdst = sm_base + wsm_off + ((uint32_t)buf * 192u + (uint32_t)tid) * 16u;
            cpa16(wdst, srcW);
        }
    };

    load_chunk(0, 0);
    asm volatile("cp.async.commit_group;");

    for (int kc = 0; kc < NKC; ++kc) {
        const int buf = kc & 1;
        asm volatile("cp.async.wait_group 0;");
        __syncthreads();   // load kc visible; prev compute done with buf^1
        if (kc + 1 < NKC) {
            load_chunk(kc + 1, buf ^ 1);
            asm volatile("cp.async.commit_group;");
        }

        const float* xs = sm + buf * TT * XP;
        const uint4* w4 = reinterpret_cast<const uint4*>(sm + 2 * TT * XP) + buf * 192;

        unsigned ah[2][4], al[2][4];
#pragma unroll
        for (int mt = 0; mt < 2; ++mt) {
            int r0 = R + mt * 16 + grp;
            float2 x0 = *reinterpret_cast<const float2*>(xs + r0 * XP + 2 * tig);
            float2 x1 = *reinterpret_cast<const float2*>(xs + (r0 + 8) * XP + 2 * tig);
            float2 x2 = *reinterpret_cast<const float2*>(xs + r0 * XP + 8 + 2 * tig);
            float2 x3 = *reinterpret_cast<const float2*>(xs + (r0 + 8) * XP + 8 + 2 * tig);
            ah[mt][0] = pk2(x0.x, x0.y); al[mt][0] = pkres(x0.x, x0.y, ah[mt][0]);
            ah[mt][1] = pk2(x1.x, x1.y); al[mt][1] = pkres(x1.x, x1.y, ah[mt][1]);
            ah[mt][2] = pk2(x2.x, x2.y); al[mt][2] = pkres(x2.x, x2.y, ah[mt][2]);
            ah[mt][3] = pk2(x3.x, x3.y); al[mt][3] = pkres(x3.x, x3.y, ah[mt][3]);
        }
#pragma unroll
        for (int nt = 0; nt < 6; ++nt) {
            uint4 q4 = w4[nt * 32 + lane];     // one LDS.128, conflict-free
            unsigned bh[2] = {q4.x, q4.y};
            unsigned bl[2] = {q4.z, q4.w};
#pragma unroll
            for (int mt = 0; mt < 2; ++mt) {
                mma_bf16(acc[mt][nt], ah[mt], bh);
                mma_bf16(acc[mt][nt], ah[mt], bl);
                mma_bf16(acc[mt][nt], al[mt], bh);
            }
        }
    }
    __syncthreads();   // all warps done reading x/W buffers before scatter clobbers

    // ===== scatter qkv into fragment-packed layouts (numerics identical) =========
#pragma unroll
    for (int mt = 0; mt < 2; ++mt)
#pragma unroll
        for (int nt = 0; nt < 6; ++nt)
#pragma unroll
            for (int e = 0; e < 4; ++e) {
                int r   = R + mt * 16 + grp + ((e >= 2) ? 8 : 0);
                int cgl = nt * 8 + 2 * tig + (e & 1);
                float v = acc[mt][nt][e];
                if (cgl < 16) {
                    int j  = r >> 4, gp = r & 7, h = (r >> 3) & 1;
                    int k8 = cgl >> 3, cw = cgl & 7;
                    int tp = cw & 3, chf = cw >> 2;
                    q_pk[((j * 2 + k8) * 32 + gp * 4 + tp) * 4 + chf * 2 + h] =
                        __uint_as_float(f2tf(v));
                } else if (cgl < 32) {
                    int c = cgl - 16;
                    int bw = r >> 5, nt2 = (r >> 3) & 3, gp = r & 7;
                    int k8 = c >> 3, tp = c & 3, hf = (c >> 2) & 1;
                    k_pk[(((bw * 2 + k8) * 2 + (nt2 >> 1)) * 32 + gp * 4 + tp) * 4 +
                         (nt2 & 1) * 2 + hf] = __uint_as_float(f2tf(v));
                } else {
                    int d = cgl - 32;
                    int bw = r >> 5, cv = (r >> 4) & 1, sw = r & 15;
                    int tp = (sw & 7) >> 1;
                    int elem = ((sw >> 3) << 1) + (sw & 1);
                    int ntv = d >> 3, gp = d & 7;
                    v_pk[(((bw * 2 + cv) * 2 + ntv) * 32 + gp * 4 + tp) * 4 + elem] = v;
                }
            }
    __syncthreads();

    // ========= Phase 2: attention, column softmax, single barrier per block =======
    const int rb0 = warp * 16;
    const int rb1 = 240 - warp * 16;
    int rb[2] = {rb0, rb1};

    const uint4*  qp4 = reinterpret_cast<const uint4*>(q_pk);
    const uint4*  kp4 = reinterpret_cast<const uint4*>(k_pk);
    const float4* vp4 = reinterpret_cast<const float4*>(v_pk);

    float oacc[2][2][4];
#pragma unroll
    for (int mt = 0; mt < 2; ++mt)
#pragma unroll
        for (int nt = 0; nt < 2; ++nt)
#pragma unroll
            for (int e = 0; e < 4; ++e) oacc[mt][nt][e] = 0.f;

    for (int blk = 0; blk < TT / 32; ++blk) {
        const int s0 = blk * 32;
        const bool act0 = (warp >= 2 * blk);
        const bool act1 = ((15 - warp) >= 2 * blk);
        const bool anyact = act1;
        float* psumP = psum + (blk & 1) * 256;

        float ef[2][4][4];
#pragma unroll
        for (int mt = 0; mt < 2; ++mt)
#pragma unroll
            for (int nt = 0; nt < 4; ++nt)
#pragma unroll
                for (int e = 0; e < 4; ++e) ef[mt][nt][e] = 0.f;

        float ps[4][2];
#pragma unroll
        for (int nt = 0; nt < 4; ++nt) { ps[nt][0] = 0.f; ps[nt][1] = 0.f; }

        if (anyact) {
            // S = q k^T (K=16), tf32, packed fragments
#pragma unroll
            for (int k8 = 0; k8 < 2; ++k8) {
                unsigned aq[2][4];
#pragma unroll
                for (int mt = 0; mt < 2; ++mt) {
                    if (mt == 0 && !act0) continue;
                    int j = rb[mt] >> 4;
                    uint4 a4 = qp4[(j * 2 + k8) * 32 + lane];
                    aq[mt][0] = a4.x; aq[mt][1] = a4.y;
                    aq[mt][2] = a4.z; aq[mt][3] = a4.w;
                }
                uint4 kg0 = kp4[((blk * 2 + k8) * 2 + 0) * 32 + lane];
                uint4 kg1 = kp4[((blk * 2 + k8) * 2 + 1) * 32 + lane];
#pragma unroll
                for (int nt = 0; nt < 4; ++nt) {
                    unsigned bb[2];
                    bb[0] = (nt == 0) ? kg0.x : (nt == 1) ? kg0.z : (nt == 2) ? kg1.x : kg1.z;
                    bb[1] = (nt == 0) ? kg0.y : (nt == 1) ? kg0.w : (nt == 2) ? kg1.y : kg1.w;
                    if (act0) mma_tf32(ef[0][nt], aq[0], bb);
                    mma_tf32(ef[1][nt], aq[1], bb);
                }
            }
            // mask + exp
#pragma unroll
            for (int mt = 0; mt < 2; ++mt) {
                if (mt == 0 && !act0) {
#pragma unroll
                    for (int nt = 0; nt < 4; ++nt)
#pragma unroll
                        for (int e = 0; e < 4; ++e) ef[0][nt][e] = 0.f;
                    continue;
                }
#pragma unroll
                for (int nt = 0; nt < 4; ++nt)
#pragma unroll
                    for (int e = 0; e < 4; ++e) {
                        int r  = rb[mt] + grp + ((e >= 2) ? 8 : 0);
                        int sg = s0 + nt * 8 + 2 * tig + (e & 1);
                        ef[mt][nt][e] = (sg <= r) ? __expf(ef[mt][nt][e]) : 0.f;
                    }
            }
            // per-column partial sums over this warp's 32 rows
#pragma unroll
            for (int nt = 0; nt < 4; ++nt)
#pragma unroll
                for (int bb2 = 0; bb2 < 2; ++bb2) {
                    float s = ef[0][nt][bb2] + ef[0][nt][bb2 + 2]
                            + ef[1][nt][bb2] + ef[1][nt][bb2 + 2];
                    s += __shfl_xor_sync(0xffffffffu, s, 4);
                    s += __shfl_xor_sync(0xffffffffu, s, 8);
                    s += __shfl_xor_sync(0xffffffffu, s, 16);
                    ps[nt][bb2] = s;
                }
        }
        if (grp == 0) {
#pragma unroll
            for (int nt = 0; nt < 4; ++nt) {
                psumP[warp * 32 + nt * 8 + 2 * tig]     = ps[nt][0];
                psumP[warp * 32 + nt * 8 + 2 * tig + 1] = ps[nt][1];
            }
        }
        __syncthreads();   // single barrier per block (parity buffer handles WAR)

        float rv;
        {
            float tot = 0.f;
#pragma unroll
            for (int w = 0; w < 8; ++w) tot += psumP[w * 32 + lane];
            rv = 1.0f / tot;
        }

        if (anyact) {
            // PV in bf16 3-term, k16; packed v fragments
#pragma unroll
            for (int ch = 0; ch < 2; ++ch) {
                unsigned pah[2][4], pal[2][4];
#pragma unroll
                for (int mt = 0; mt < 2; ++mt) {
                    if (mt == 0 && !act0) continue;
#pragma unroll
                    for (int hq = 0; hq < 2; ++hq) {
                        float e0 = ef[mt][2 * ch + hq][0];
                        float e1 = ef[mt][2 * ch + hq][1];
                        float e2 = ef[mt][2 * ch + hq][2];
                        float e3 = ef[mt][2 * ch + hq][3];
                        pah[mt][2 * hq]     = pk2(e0, e1);
                        pal[mt][2 * hq]     = pkres(e0, e1, pah[mt][2 * hq]);
                        pah[mt][2 * hq + 1] = pk2(e2, e3);
                        pal[mt][2 * hq + 1] = pkres(e2, e3, pah[mt][2 * hq + 1]);
                    }
                }
                float r0 = __shfl_sync(0xffffffffu, rv, ch * 16 + 2 * tig);
                float r1 = __shfl_sync(0xffffffffu, rv, ch * 16 + 2 * tig + 1);
                float r2 = __shfl_sync(0xffffffffu, rv, ch * 16 + 8 + 2 * tig);
                float r3 = __shfl_sync(0xffffffffu, rv, ch * 16 + 9 + 2 * tig);
                float4 vf[2];
                vf[0] = vp4[((blk * 2 + ch) * 2 + 0) * 32 + lane];
                vf[1] = vp4[((blk * 2 + ch) * 2 + 1) * 32 + lane];
#pragma unroll
                for (int nt = 0; nt < 2; ++nt) {
                    float b0 = vf[nt].x * r0;
                    float b1 = vf[nt].y * r1;
                    float b2 = vf[nt].z * r2;
                    float b3 = vf[nt].w * r3;
                    unsigned bh[2], bl[2];
                    bh[0] = pk2(b0, b1); bl[0] = pkres(b0, b1, bh[0]);
                    bh[1] = pk2(b2, b3); bl[1] = pkres(b2, b3, bh[1]);
                    if (act0) {
                        mma_bf16(oacc[0][nt], pah[0], bh);
                        mma_bf16(oacc[0][nt], pah[0], bl);
                        mma_bf16(oacc[0][nt], pal[0], bh);
                    }
                    mma_bf16(oacc[1][nt], pah[1], bh);
                    mma_bf16(oacc[1][nt], pah[1], bl);
                    mma_bf16(oacc[1][nt], pal[1], bh);
                }
            }
        }
    }

    float* ob = out + (size_t)b * TT * HSZ;
#pragma unroll
    for (int mt = 0; mt < 2; ++mt)
#pragma unroll
        for (int nt = 0; nt < 2; ++nt) {
            int r0 = rb[mt] + grp;
            int c  = nt * 8 + 2 * tig;
            *reinterpret_cast<float2*>(ob + r0 * HSZ + c) =
                make_float2(oacc[mt][nt][0], oacc[mt][nt][1]);
            *reinterpret_cast<float2*>(ob + (r0 + 8) * HSZ + c) =
                make_float2(oacc[mt][nt][2], oacc[mt][nt][3]);
        }
}

extern "C" void kernel_launch(void* const* d_in, const int* in_sizes, int n_in,
                              void* d_out, int out_size) {
    const float* x  = (const float*)d_in[0];
    const float* wk = (const float*)d_in[1];
    const float* wq = (const float*)d_in[2];
    const float* wv = (const float*)d_in[3];
    float* out      = (float*)d_out;

    const int B = in_sizes[0] / (TT * CC);  // 512

    cudaFuncSetAttribute(head_fused_kernel,
                         cudaFuncAttributeMaxDynamicSharedMemorySize, SMEM_BYTES);

    pack_w_kernel<<<18, 256>>>(wk, wq, wv);
    head_fused_kernel<<<B, 256, SMEM_BYTES>>>(x, out);
}

// round 16
// speedup vs baseline: 1.2207x; 1.2207x over previous
#include <cuda_runtime.h>
#include <cstdint>

// Problem constants: B=512, T=256, C=384, HS=16
#define TT   256
#define CC   384
#define HSZ  16
#define KCH  32          // K-chunk for projection
#define NKC  (CC/KCH)    // 12
#define XP1  36          // x tile row stride (floats), conflict-free (proven)
#define QKP  20          // q/k row stride
#define VPD  28          // v row stride (proven)

// packed W: 24 k16-chunks x 48 cb x 4 tig, uint4 = {bh0, bh1, bl0, bl1}
// q-columns pre-scaled by C^-0.5 * log2(e)  (softmax uses exp2)
__device__ uint4 g_w4[24 * 192];

// smem (floats):
//  phase1: x 2*256*36 = 18432 + W4 2*384*4 = 3072 -> 21504 f = 86016 B (max)
//  phase2: q[256*20] k[256*20] v[256*28] psum[2*256] = 17920 f
#define SMEM_FLOATS (2 * TT * XP1 + 2 * 384 * 4)
#define SMEM_BYTES  (SMEM_FLOATS * 4)

__device__ __forceinline__ unsigned f2tf(float f) {
    unsigned r;
    asm("cvt.rna.tf32.f32 %0, %1;" : "=r"(r) : "f"(f));
    return r;
}
__device__ __forceinline__ unsigned pk2(float lo, float hi) {
    unsigned r;
    asm("cvt.rn.bf16x2.f32 %0, %1, %2;" : "=r"(r) : "f"(hi), "f"(lo));
    return r;
}
__device__ __forceinline__ float bflo(unsigned u) { return __uint_as_float(u << 16); }
__device__ __forceinline__ float bfhi(unsigned u) { return __uint_as_float(u & 0xffff0000u); }
__device__ __forceinline__ unsigned pkres(float lo, float hi, unsigned h) {
    return pk2(lo - bflo(h), hi - bfhi(h));
}

__device__ __forceinline__ void mma_tf32(float* c, const unsigned* a, const unsigned* b) {
    asm volatile(
        "mma.sync.aligned.m16n8k8.row.col.f32.tf32.tf32.f32 "
        "{%0,%1,%2,%3}, {%4,%5,%6,%7}, {%8,%9}, {%0,%1,%2,%3};"
        : "+f"(c[0]), "+f"(c[1]), "+f"(c[2]), "+f"(c[3])
        : "r"(a[0]), "r"(a[1]), "r"(a[2]), "r"(a[3]), "r"(b[0]), "r"(b[1]));
}
__device__ __forceinline__ void mma_bf16(float* c, const unsigned* a, const unsigned* b) {
    asm volatile(
        "mma.sync.aligned.m16n8k16.row.col.f32.bf16.bf16.f32 "
        "{%0,%1,%2,%3}, {%4,%5,%6,%7}, {%8,%9}, {%0,%1,%2,%3};"
        : "+f"(c[0]), "+f"(c[1]), "+f"(c[2]), "+f"(c[3])
        : "r"(a[0]), "r"(a[1]), "r"(a[2]), "r"(a[3]), "r"(b[0]), "r"(b[1]));
}
// x stream: L1-bypass (zero reuse)
__device__ __forceinline__ void cpa16cg(uint32_t saddr, const void* g) {
    asm volatile("cp.async.cg.shared.global [%0], [%1], 16;" :: "r"(saddr), "l"(g));
}
// W: keep L1 caching (hot across 512 CTAs)
__device__ __forceinline__ void cpa16(uint32_t saddr, const void* g) {
    asm volatile("cp.async.ca.shared.global [%0], [%1], 16;" :: "r"(saddr), "l"(g));
}

// ===== pre-kernel: pack W into B-fragment uint4 layout =====
// q-cols scaled by C^-0.5 * log2(e) so phase-2 softmax is a bare exp2
__global__ void pack_w_kernel(const float* __restrict__ wk,
                              const float* __restrict__ wq,
                              const float* __restrict__ wv)
{
    int f = blockIdx.x * 256 + threadIdx.x;      // 0..4607
    if (f >= 24 * 192) return;
    int chunk = f / 192;
    int rem   = f % 192;
    int cb    = rem / 4;
    int tg    = rem % 4;

    const float* w;
    int c;
    float s = 1.0f;
    if (cb < 16)      { w = wq; c = cb;      s = rsqrtf((float)CC) * 1.4426950408889634f; }
    else if (cb < 32) { w = wk; c = cb - 16; }
    else              { w = wv; c = cb - 32; }

    int kA = chunk * 16 + 2 * tg;
    int kB = kA + 8;
    float a0 = w[kA * HSZ + c] * s;
    float a1 = w[(kA + 1) * HSZ + c] * s;
    float b0 = w[kB * HSZ + c] * s;
    float b1 = w[(kB + 1) * HSZ + c] * s;
    unsigned h0 = pk2(a0, a1);
    unsigned h1 = pk2(b0, b1);
    uint4 r;
    r.x = h0;
    r.y = h1;
    r.z = pkres(a0, a1, h0);
    r.w = pkres(b0, b1, h1);
    g_w4[f] = r;
}

// ====================== fused kernel: projection + attention ======================
__global__ void __launch_bounds__(256, 2) head_fused_kernel(
    const float* __restrict__ x,
    float* __restrict__ out)
{
    extern __shared__ float sm[];
    const int b    = blockIdx.x;
    const int tid  = threadIdx.x;
    const int lane = tid & 31;
    const int warp = tid >> 5;
    const int grp  = lane >> 2;  // 0..7
    const int tig  = lane & 3;   // 0..3

    const uint32_t sm_base = (uint32_t)__cvta_generic_to_shared(sm);

    // phase-2 smem views (overlap phase-1 region)
    float* q_s  = sm;
    float* k_s  = q_s + TT * QKP;
    float* v_s  = k_s + TT * QKP;
    float* psum = v_s + TT * VPD;     // [2][256] parity-buffered

    const float* xb = x + (size_t)b * TT * CC;
    const int R = warp * 32;

    // ======= Phase 1: qkv = x @ Wpacked, bf16 3-term, one barrier per kc =========
    float acc[2][6][4];
#pragma unroll
    for (int mt = 0; mt < 2; ++mt)
#pragma unroll
        for (int nt = 0; nt < 6; ++nt)
#pragma unroll
            for (int e = 0; e < 4; ++e) acc[mt][nt][e] = 0.f;

    const uint32_t wsm_off = (uint32_t)(2 * TT * XP1) * 4u;   // byte offset of W4 region

    auto load_chunk = [&](int kc, int buf) {
        const float* xg = xb + kc * KCH;
        uint32_t xs_a = sm_base + (uint32_t)(buf * TT * XP1) * 4u;
#pragma unroll
        for (int i = 0; i < 8; ++i) {
            int row = (tid >> 3) + i * 32;
            int c4  = (tid & 7) * 4;
            cpa16cg(xs_a + (uint32_t)(row * XP1 + c4) * 4u, xg + row * CC + c4);
        }
        // W: linear copy of 384 uint4 (2 chunks) into this buffer
        const uint4* srcW = g_w4 + kc * 384;
        uint32_t wdst = sm_base + wsm_off + (uint32_t)buf * 384u * 16u;
#pragma unroll
        for (int i = 0; i < 2; ++i) {
            int f = tid + i * 256;
            if (f < 384) cpa16(wdst + (uint32_t)f * 16u, srcW + f);
        }
    };

    load_chunk(0, 0);
    asm volatile("cp.async.commit_group;");

    for (int kc = 0; kc < NKC; ++kc) {
        const int buf = kc & 1;
        asm volatile("cp.async.wait_group 0;");
        __syncthreads();   // load kc visible to all; prev compute done with buf^1
        if (kc + 1 < NKC) {
            load_chunk(kc + 1, buf ^ 1);
            asm volatile("cp.async.commit_group;");
        }

        const float* xs = sm + buf * TT * XP1;
        const uint4* w4 = reinterpret_cast<const uint4*>(sm + 2 * TT * XP1) + buf * 384;

#pragma unroll
        for (int ch = 0; ch < 2; ++ch) {          // two k16 chunks per kc
            const int ko = ch * 16;
            unsigned ah[2][4], al[2][4];
#pragma unroll
            for (int mt = 0; mt < 2; ++mt) {
                int r0 = R + mt * 16 + grp;
                float2 x0 = *reinterpret_cast<const float2*>(xs + r0 * XP1 + ko + 2 * tig);
                float2 x1 = *reinterpret_cast<const float2*>(xs + (r0 + 8) * XP1 + ko + 2 * tig);
                float2 x2 = *reinterpret_cast<const float2*>(xs + r0 * XP1 + ko + 8 + 2 * tig);
                float2 x3 = *reinterpret_cast<const float2*>(xs + (r0 + 8) * XP1 + ko + 8 + 2 * tig);
                ah[mt][0] = pk2(x0.x, x0.y); al[mt][0] = pkres(x0.x, x0.y, ah[mt][0]);
                ah[mt][1] = pk2(x1.x, x1.y); al[mt][1] = pkres(x1.x, x1.y, ah[mt][1]);
                ah[mt][2] = pk2(x2.x, x2.y); al[mt][2] = pkres(x2.x, x2.y, ah[mt][2]);
                ah[mt][3] = pk2(x3.x, x3.y); al[mt][3] = pkres(x3.x, x3.y, ah[mt][3]);
            }
            const uint4* wc = w4 + ch * 192;
#pragma unroll
            for (int nt = 0; nt < 6; ++nt) {
                uint4 q4 = wc[nt * 32 + lane];     // one LDS.128, conflict-free
                unsigned bh[2] = {q4.x, q4.y};
                unsigned bl[2] = {q4.z, q4.w};
#pragma unroll
                for (int mt = 0; mt < 2; ++mt) {
                    mma_bf16(acc[mt][nt], ah[mt], bh);
                    mma_bf16(acc[mt][nt], ah[mt], bl);
                    mma_bf16(acc[mt][nt], al[mt], bh);
                }
            }
        }
    }
    __syncthreads();   // all warps done reading x buffers before scatter clobbers

    // scatter qkv; scales pre-folded into W; q/k pre-rounded tf32, v raw fp32
#pragma unroll
    for (int mt = 0; mt < 2; ++mt)
#pragma unroll
        for (int nt = 0; nt < 6; ++nt)
#pragma unroll
            for (int e = 0; e < 4; ++e) {
                int r   = R + mt * 16 + grp + ((e >= 2) ? 8 : 0);
                int cgl = nt * 8 + 2 * tig + (e & 1);
                float v = acc[mt][nt][e];
                if (cgl < 16)      q_s[r * QKP + cgl]        = __uint_as_float(f2tf(v));
                else if (cgl < 32) k_s[r * QKP + (cgl - 16)] = __uint_as_float(f2tf(v));
                else               v_s[r * VPD + (cgl - 32)] = v;
            }
    __syncthreads();

    // ========= Phase 2: attention, column softmax (exp2), 1 barrier/block ========
    const int rb0 = warp * 16;
    const int rb1 = 240 - warp * 16;
    int rb[2] = {rb0, rb1};

    float oacc[2][2][4];
#pragma unroll
    for (int mt = 0; mt < 2; ++mt)
#pragma unroll
        for (int nt = 0; nt < 2; ++nt)
#pragma unroll
            for (int e = 0; e < 4; ++e) oacc[mt][nt][e] = 0.f;

    for (int blk = 0; blk < TT / 32; ++blk) {
        const int s0 = blk * 32;
        const bool act0 = (warp >= 2 * blk);
        const bool act1 = ((15 - warp) >= 2 * blk);
        const bool anyact = act1;
        float* psumP = psum + (blk & 1) * 256;

        float ef[2][4][4];
#pragma unroll
        for (int mt = 0; mt < 2; ++mt)
#pragma unroll
            for (int nt = 0; nt < 4; ++nt)
#pragma unroll
                for (int e = 0; e < 4; ++e) ef[mt][nt][e] = 0.f;

        float ps[4][2];
#pragma unroll
        for (int nt = 0; nt < 4; ++nt) { ps[nt][0] = 0.f; ps[nt][1] = 0.f; }

        if (anyact) {
            // S = q k^T (K=16), tf32, operands pre-rounded (q already has log2e)
#pragma unroll
            for (int k8 = 0; k8 < 2; ++k8) {
                const int ko = k8 * 8;
                unsigned aq[2][4];
#pragma unroll
                for (int mt = 0; mt < 2; ++mt) {
                    if (mt == 0 && !act0) continue;
                    int r0 = rb[mt] + grp;
                    aq[mt][0] = __float_as_uint(q_s[r0 * QKP + ko + tig]);
                    aq[mt][1] = __float_as_uint(q_s[(r0 + 8) * QKP + ko + tig]);
                    aq[mt][2] = __float_as_uint(q_s[r0 * QKP + ko + tig + 4]);
                    aq[mt][3] = __float_as_uint(q_s[(r0 + 8) * QKP + ko + tig + 4]);
                }
#pragma unroll
                for (int nt = 0; nt < 4; ++nt) {
                    int sc = s0 + nt * 8 + grp;
                    unsigned bb[2];
                    bb[0] = __float_as_uint(k_s[sc * QKP + ko + tig]);
                    bb[1] = __float_as_uint(k_s[sc * QKP + ko + tig + 4]);
                    if (act0) mma_tf32(ef[0][nt], aq[0], bb);
                    mma_tf32(ef[1][nt], aq[1], bb);
                }
            }
            // mask + exp2 (log2e folded into q)
#pragma unroll
            for (int mt = 0; mt < 2; ++mt) {
                if (mt == 0 && !act0) {
#pragma unroll
                    for (int nt = 0; nt < 4; ++nt)
#pragma unroll
                        for (int e = 0; e < 4; ++e) ef[0][nt][e] = 0.f;
                    continue;
                }
#pragma unroll
                for (int nt = 0; nt < 4; ++nt)
#pragma unroll
                    for (int e = 0; e < 4; ++e) {
                        int r  = rb[mt] + grp + ((e >= 2) ? 8 : 0);
                        int sg = s0 + nt * 8 + 2 * tig + (e & 1);
                        ef[mt][nt][e] = (sg <= r) ? exp2f(ef[mt][nt][e]) : 0.f;
                    }
            }
            // per-column partial sums over this warp's 32 rows
#pragma unroll
            for (int nt = 0; nt < 4; ++nt)
#pragma unroll
                for (int bb2 = 0; bb2 < 2; ++bb2) {
                    float s = ef[0][nt][bb2] + ef[0][nt][bb2 + 2]
                            + ef[1][nt][bb2] + ef[1][nt][bb2 + 2];
                    s += __shfl_xor_sync(0xffffffffu, s, 4);
                    s += __shfl_xor_sync(0xffffffffu, s, 8);
                    s += __shfl_xor_sync(0xffffffffu, s, 16);
                    ps[nt][bb2] = s;
                }
        }
        if (grp == 0) {
#pragma unroll
            for (int nt = 0; nt < 4; ++nt) {
                psumP[warp * 32 + nt * 8 + 2 * tig]     = ps[nt][0];
                psumP[warp * 32 + nt * 8 + 2 * tig + 1] = ps[nt][1];
            }
        }
        __syncthreads();   // single barrier per block (parity buffer handles WAR)

        // every warp reduces its own rinv: lane L -> 1/denom of column s0+L
        float rv;
        {
            float tot = 0.f;
#pragma unroll
            for (int w = 0; w < 8; ++w) tot += psumP[w * 32 + lane];
            rv = 1.0f / tot;
        }

        if (anyact) {
            // PV in bf16 3-term, k16 (C-frag == A-frag layout, no P shuffles)
#pragma unroll
            for (int ch = 0; ch < 2; ++ch) {
                const int sb = s0 + ch * 16;
                unsigned pah[2][4], pal[2][4];
#pragma unroll
                for (int mt = 0; mt < 2; ++mt) {
                    if (mt == 0 && !act0) continue;
#pragma unroll
                    for (int hq = 0; hq < 2; ++hq) {
                        float e0 = ef[mt][2 * ch + hq][0];
                        float e1 = ef[mt][2 * ch + hq][1];
                        float e2 = ef[mt][2 * ch + hq][2];
                        float e3 = ef[mt][2 * ch + hq][3];
                        pah[mt][2 * hq]     = pk2(e0, e1);
                        pal[mt][2 * hq]     = pkres(e0, e1, pah[mt][2 * hq]);
                        pah[mt][2 * hq + 1] = pk2(e2, e3);
                        pal[mt][2 * hq + 1] = pkres(e2, e3, pah[mt][2 * hq + 1]);
                    }
                }
                float r0 = __shfl_sync(0xffffffffu, rv, ch * 16 + 2 * tig);
                float r1 = __shfl_sync(0xffffffffu, rv, ch * 16 + 2 * tig + 1);
                float r2 = __shfl_sync(0xffffffffu, rv, ch * 16 + 8 + 2 * tig);
                float r3 = __shfl_sync(0xffffffffu, rv, ch * 16 + 9 + 2 * tig);
#pragma unroll
                for (int nt = 0; nt < 2; ++nt) {
                    int d = nt * 8 + grp;
                    float b0 = v_s[(sb + 2 * tig)     * VPD + d] * r0;
                    float b1 = v_s[(sb + 2 * tig + 1) * VPD + d] * r1;
                    float b2 = v_s[(sb + 8 + 2 * tig) * VPD + d] * r2;
                    float b3 = v_s[(sb + 9 + 2 * tig) * VPD + d] * r3;
                    unsigned bh[2], bl[2];
                    bh[0] = pk2(b0, b1); bl[0] = pkres(b0, b1, bh[0]);
                    bh[1] = pk2(b2, b3); bl[1] = pkres(b2, b3, bh[1]);
                    if (act0) {
                        mma_bf16(oacc[0][nt], pah[0], bh);
                        mma_bf16(oacc[0][nt], pah[0], bl);
                        mma_bf16(oacc[0][nt], pal[0], bh);
                    }
                    mma_bf16(oacc[1][nt], pah[1], bh);
                    mma_bf16(oacc[1][nt], pah[1], bl);
                    mma_bf16(oacc[1][nt], pal[1], bh);
                }
            }
        }
    }

    float* ob = out + (size_t)b * TT * HSZ;
#pragma unroll
    for (int mt = 0; mt < 2; ++mt)
#pragma unroll
        for (int nt = 0; nt < 2; ++nt) {
            int r0 = rb[mt] + grp;
            int c  = nt * 8 + 2 * tig;
            *reinterpret_cast<float2*>(ob + r0 * HSZ + c) =
                make_float2(oacc[mt][nt][0], oacc[mt][nt][1]);
            *reinterpret_cast<float2*>(ob + (r0 + 8) * HSZ + c) =
                make_float2(oacc[mt][nt][2], oacc[mt][nt][3]);
        }
}

extern "C" void kernel_launch(void* const* d_in, const int* in_sizes, int n_in,
                              void* d_out, int out_size) {
    const float* x  = (const float*)d_in[0];
    const float* wk = (const float*)d_in[1];
    const float* wq = (const float*)d_in[2];
    const float* wv = (const float*)d_in[3];
    float* out      = (float*)d_out;

    const int B = in_sizes[0] / (TT * CC);  // 512

    cudaFuncSetAttribute(head_fused_kernel,
                         cudaFuncAttributeMaxDynamicSharedMemorySize, SMEM_BYTES);

    pack_w_kernel<<<18, 256>>>(wk, wq, wv);
    head_fused_kernel<<<B, 256, SMEM_BYTES>>>(x, out);
}

// round 17
// speedup vs baseline: 1.2493x; 1.0234x over previous
#include <cuda_runtime.h>
#include <cstdint>

// Problem constants: B=512, T=256, C=384, HS=16
#define TT   256
#define CC   384
#define HSZ  16
#define KCH  32          // K-chunk for projection
#define NKC  (CC/KCH)    // 12
#define XP1  36          // x tile row stride (floats), conflict-free (proven)
#define QKP  20          // q/k row stride
#define VPD  28          // v row stride (proven)

// packed W: 24 k16-chunks x 48 cb x 4 tig, uint4 = {bh0, bh1, bl0, bl1}
// q-columns pre-scaled by C^-0.5 * log2(e)  (softmax uses exp2)
__device__ uint4 g_w4[24 * 192];

// smem (floats):
//  phase1: x 2*256*36 = 18432 + W4 2*384*4 = 3072 -> 21504 f = 86016 B (max)
//  phase2: q[256*20] k[256*20] v[256*28] psum[2*256] = 17920 f
#define SMEM_FLOATS (2 * TT * XP1 + 2 * 384 * 4)
#define SMEM_BYTES  (SMEM_FLOATS * 4)

__device__ __forceinline__ unsigned f2tf(float f) {
    unsigned r;
    asm("cvt.rna.tf32.f32 %0, %1;" : "=r"(r) : "f"(f));
    return r;
}
__device__ __forceinline__ unsigned pk2(float lo, float hi) {
    unsigned r;
    asm("cvt.rn.bf16x2.f32 %0, %1, %2;" : "=r"(r) : "f"(hi), "f"(lo));
    return r;
}
__device__ __forceinline__ float bflo(unsigned u) { return __uint_as_float(u << 16); }
__device__ __forceinline__ float bfhi(unsigned u) { return __uint_as_float(u & 0xffff0000u); }
__device__ __forceinline__ unsigned pkres(float lo, float hi, unsigned h) {
    return pk2(lo - bflo(h), hi - bfhi(h));
}
// truncation split for x: hi = top-16 bits (PRMT pack), residual exact then rounded
__device__ __forceinline__ unsigned pk2t(unsigned u0, unsigned u1) {
    return __byte_perm(u0, u1, 0x7632);   // {u0.hi16, u1.hi16}
}
__device__ __forceinline__ unsigned pkrest(float x0, float x1, unsigned u0, unsigned u1) {
    return pk2(x0 - __uint_as_float(u0 & 0xffff0000u),
               x1 - __uint_as_float(u1 & 0xffff0000u));
}

__device__ __forceinline__ void mma_tf32(float* c, const unsigned* a, const unsigned* b) {
    asm volatile(
        "mma.sync.aligned.m16n8k8.row.col.f32.tf32.tf32.f32 "
        "{%0,%1,%2,%3}, {%4,%5,%6,%7}, {%8,%9}, {%0,%1,%2,%3};"
        : "+f"(c[0]), "+f"(c[1]), "+f"(c[2]), "+f"(c[3])
        : "r"(a[0]), "r"(a[1]), "r"(a[2]), "r"(a[3]), "r"(b[0]), "r"(b[1]));
}
__device__ __forceinline__ void mma_bf16(float* c, const unsigned* a, const unsigned* b) {
    asm volatile(
        "mma.sync.aligned.m16n8k16.row.col.f32.bf16.bf16.f32 "
        "{%0,%1,%2,%3}, {%4,%5,%6,%7}, {%8,%9}, {%0,%1,%2,%3};"
        : "+f"(c[0]), "+f"(c[1]), "+f"(c[2]), "+f"(c[3])
        : "r"(a[0]), "r"(a[1]), "r"(a[2]), "r"(a[3]), "r"(b[0]), "r"(b[1]));
}
__device__ __forceinline__ void cpa16(uint32_t saddr, const void* g) {
    asm volatile("cp.async.ca.shared.global [%0], [%1], 16;" :: "r"(saddr), "l"(g));
}

// ===== pre-kernel: pack W into B-fragment uint4 layout =====
// q-cols scaled by C^-0.5 * log2(e) so phase-2 softmax is a bare exp2
__global__ void pack_w_kernel(const float* __restrict__ wk,
                              const float* __restrict__ wq,
                              const float* __restrict__ wv)
{
    int f = blockIdx.x * 256 + threadIdx.x;      // 0..4607
    if (f >= 24 * 192) return;
    int chunk = f / 192;
    int rem   = f % 192;
    int cb    = rem / 4;
    int tg    = rem % 4;

    const float* w;
    int c;
    float s = 1.0f;
    if (cb < 16)      { w = wq; c = cb;      s = rsqrtf((float)CC) * 1.4426950408889634f; }
    else if (cb < 32) { w = wk; c = cb - 16; }
    else              { w = wv; c = cb - 32; }

    int kA = chunk * 16 + 2 * tg;
    int kB = kA + 8;
    float a0 = w[kA * HSZ + c] * s;
    float a1 = w[(kA + 1) * HSZ + c] * s;
    float b0 = w[kB * HSZ + c] * s;
    float b1 = w[(kB + 1) * HSZ + c] * s;
    unsigned h0 = pk2(a0, a1);
    unsigned h1 = pk2(b0, b1);
    uint4 r;
    r.x = h0;
    r.y = h1;
    r.z = pkres(a0, a1, h0);
    r.w = pkres(b0, b1, h1);
    g_w4[f] = r;
}

// ====================== fused kernel: projection + attention ======================
__global__ void __launch_bounds__(256, 2) head_fused_kernel(
    const float* __restrict__ x,
    float* __restrict__ out)
{
    extern __shared__ float sm[];
    const int b    = blockIdx.x;
    const int tid  = threadIdx.x;
    const int lane = tid & 31;
    const int warp = tid >> 5;
    const int grp  = lane >> 2;  // 0..7
    const int tig  = lane & 3;   // 0..3

    const uint32_t sm_base = (uint32_t)__cvta_generic_to_shared(sm);

    // phase-2 smem views (overlap phase-1 region)
    float* q_s  = sm;
    float* k_s  = q_s + TT * QKP;
    float* v_s  = k_s + TT * QKP;
    float* psum = v_s + TT * VPD;     // [2][256] parity-buffered

    const float* xb = x + (size_t)b * TT * CC;
    const int R = warp * 32;

    // ======= Phase 1: qkv = x @ Wpacked, bf16 3-term, one barrier per kc =========
    float acc[2][6][4];
#pragma unroll
    for (int mt = 0; mt < 2; ++mt)
#pragma unroll
        for (int nt = 0; nt < 6; ++nt)
#pragma unroll
            for (int e = 0; e < 4; ++e) acc[mt][nt][e] = 0.f;

    const uint32_t wsm_off = (uint32_t)(2 * TT * XP1) * 4u;   // byte offset of W4 region

    auto load_chunk = [&](int kc, int buf) {
        const float* xg = xb + kc * KCH;
        uint32_t xs_a = sm_base + (uint32_t)(buf * TT * XP1) * 4u;
#pragma unroll
        for (int i = 0; i < 8; ++i) {
            int row = (tid >> 3) + i * 32;
            int c4  = (tid & 7) * 4;
            cpa16(xs_a + (uint32_t)(row * XP1 + c4) * 4u, xg + row * CC + c4);
        }
        // W: linear copy of 384 uint4 (2 chunks) into this buffer
        const uint4* srcW = g_w4 + kc * 384;
        uint32_t wdst = sm_base + wsm_off + (uint32_t)buf * 384u * 16u;
#pragma unroll
        for (int i = 0; i < 2; ++i) {
            int f = tid + i * 256;
            if (f < 384) cpa16(wdst + (uint32_t)f * 16u, srcW + f);
        }
    };

    load_chunk(0, 0);
    asm volatile("cp.async.commit_group;");

    for (int kc = 0; kc < NKC; ++kc) {
        const int buf = kc & 1;
        asm volatile("cp.async.wait_group 0;");
        __syncthreads();   // load kc visible to all; prev compute done with buf^1
        if (kc + 1 < NKC) {
            load_chunk(kc + 1, buf ^ 1);
            asm volatile("cp.async.commit_group;");
        }

        const float* xs = sm + buf * TT * XP1;
        const uint4* w4 = reinterpret_cast<const uint4*>(sm + 2 * TT * XP1) + buf * 384;

#pragma unroll
        for (int ch = 0; ch < 2; ++ch) {          // two k16 chunks per kc
            const int ko = ch * 16;
            unsigned ah[2][4], al[2][4];
#pragma unroll
            for (int mt = 0; mt < 2; ++mt) {
                int r0 = R + mt * 16 + grp;
                float2 x0 = *reinterpret_cast<const float2*>(xs + r0 * XP1 + ko + 2 * tig);
                float2 x1 = *reinterpret_cast<const float2*>(xs + (r0 + 8) * XP1 + ko + 2 * tig);
                float2 x2 = *reinterpret_cast<const float2*>(xs + r0 * XP1 + ko + 8 + 2 * tig);
                float2 x3 = *reinterpret_cast<const float2*>(xs + (r0 + 8) * XP1 + ko + 8 + 2 * tig);
                unsigned u00 = __float_as_uint(x0.x), u01 = __float_as_uint(x0.y);
                unsigned u10 = __float_as_uint(x1.x), u11 = __float_as_uint(x1.y);
                unsigned u20 = __float_as_uint(x2.x), u21 = __float_as_uint(x2.y);
                unsigned u30 = __float_as_uint(x3.x), u31 = __float_as_uint(x3.y);
                ah[mt][0] = pk2t(u00, u01); al[mt][0] = pkrest(x0.x, x0.y, u00, u01);
                ah[mt][1] = pk2t(u10, u11); al[mt][1] = pkrest(x1.x, x1.y, u10, u11);
                ah[mt][2] = pk2t(u20, u21); al[mt][2] = pkrest(x2.x, x2.y, u20, u21);
                ah[mt][3] = pk2t(u30, u31); al[mt][3] = pkrest(x3.x, x3.y, u30, u31);
            }
            const uint4* wc = w4 + ch * 192;
#pragma unroll
            for (int nt = 0; nt < 6; ++nt) {
                uint4 q4 = wc[nt * 32 + lane];     // one LDS.128, conflict-free
                unsigned bh[2] = {q4.x, q4.y};
                unsigned bl[2] = {q4.z, q4.w};
#pragma unroll
                for (int mt = 0; mt < 2; ++mt) {
                    mma_bf16(acc[mt][nt], ah[mt], bh);
                    mma_bf16(acc[mt][nt], ah[mt], bl);
                    mma_bf16(acc[mt][nt], al[mt], bh);
                }
            }
        }
    }
    __syncthreads();   // all warps done reading x buffers before scatter clobbers

    // scatter qkv; scales pre-folded into W; q/k pre-rounded tf32, v raw fp32
#pragma unroll
    for (int mt = 0; mt < 2; ++mt)
#pragma unroll
        for (int nt = 0; nt < 6; ++nt)
#pragma unroll
            for (int e = 0; e < 4; ++e) {
                int r   = R + mt * 16 + grp + ((e >= 2) ? 8 : 0);
                int cgl = nt * 8 + 2 * tig + (e & 1);
                float v = acc[mt][nt][e];
                if (cgl < 16)      q_s[r * QKP + cgl]        = __uint_as_float(f2tf(v));
                else if (cgl < 32) k_s[r * QKP + (cgl - 16)] = __uint_as_float(f2tf(v));
                else               v_s[r * VPD + (cgl - 32)] = v;
            }
    __syncthreads();

    // ========= Phase 2: attention, column softmax (exp2), 1 barrier/block ========
    const int rb0 = warp * 16;
    const int rb1 = 240 - warp * 16;
    int rb[2] = {rb0, rb1};

    float oacc[2][2][4];
#pragma unroll
    for (int mt = 0; mt < 2; ++mt)
#pragma unroll
        for (int nt = 0; nt < 2; ++nt)
#pragma unroll
            for (int e = 0; e < 4; ++e) oacc[mt][nt][e] = 0.f;

    for (int blk = 0; blk < TT / 32; ++blk) {
        const int s0 = blk * 32;
        const bool act0 = (warp >= 2 * blk);
        const bool act1 = ((15 - warp) >= 2 * blk);
        const bool anyact = act1;
        float* psumP = psum + (blk & 1) * 256;

        float ef[2][4][4];
#pragma unroll
        for (int mt = 0; mt < 2; ++mt)
#pragma unroll
            for (int nt = 0; nt < 4; ++nt)
#pragma unroll
                for (int e = 0; e < 4; ++e) ef[mt][nt][e] = 0.f;

        float ps[4][2];
#pragma unroll
        for (int nt = 0; nt < 4; ++nt) { ps[nt][0] = 0.f; ps[nt][1] = 0.f; }

        if (anyact) {
            // S = q k^T (K=16), tf32, operands pre-rounded (q already has log2e)
#pragma unroll
            for (int k8 = 0; k8 < 2; ++k8) {
                const int ko = k8 * 8;
                unsigned aq[2][4];
#pragma unroll
                for (int mt = 0; mt < 2; ++mt) {
                    if (mt == 0 && !act0) continue;
                    int r0 = rb[mt] + grp;
                    aq[mt][0] = __float_as_uint(q_s[r0 * QKP + ko + tig]);
                    aq[mt][1] = __float_as_uint(q_s[(r0 + 8) * QKP + ko + tig]);
                    aq[mt][2] = __float_as_uint(q_s[r0 * QKP + ko + tig + 4]);
                    aq[mt][3] = __float_as_uint(q_s[(r0 + 8) * QKP + ko + tig + 4]);
                }
#pragma unroll
                for (int nt = 0; nt < 4; ++nt) {
                    int sc = s0 + nt * 8 + grp;
                    unsigned bb[2];
                    bb[0] = __float_as_uint(k_s[sc * QKP + ko + tig]);
                    bb[1] = __float_as_uint(k_s[sc * QKP + ko + tig + 4]);
                    if (act0) mma_tf32(ef[0][nt], aq[0], bb);
                    mma_tf32(ef[1][nt], aq[1], bb);
                }
            }
            // mask + exp2 (log2e folded into q)
#pragma unroll
            for (int mt = 0; mt < 2; ++mt) {
                if (mt == 0 && !act0) {
#pragma unroll
                    for (int nt = 0; nt < 4; ++nt)
#pragma unroll
                        for (int e = 0; e < 4; ++e) ef[0][nt][e] = 0.f;
                    continue;
                }
#pragma unroll
                for (int nt = 0; nt < 4; ++nt)
#pragma unroll
                    for (int e = 0; e < 4; ++e) {
                        int r  = rb[mt] + grp + ((e >= 2) ? 8 : 0);
                        int sg = s0 + nt * 8 + 2 * tig + (e & 1);
                        ef[mt][nt][e] = (sg <= r) ? exp2f(ef[mt][nt][e]) : 0.f;
                    }
            }
            // per-column partial sums over this warp's 32 rows
#pragma unroll
            for (int nt = 0; nt < 4; ++nt)
#pragma unroll
                for (int bb2 = 0; bb2 < 2; ++bb2) {
                    float s = ef[0][nt][bb2] + ef[0][nt][bb2 + 2]
                            + ef[1][nt][bb2] + ef[1][nt][bb2 + 2];
                    s += __shfl_xor_sync(0xffffffffu, s, 4);
                    s += __shfl_xor_sync(0xffffffffu, s, 8);
                    s += __shfl_xor_sync(0xffffffffu, s, 16);
                    ps[nt][bb2] = s;
                }
        }
        if (grp == 0) {
#pragma unroll
            for (int nt = 0; nt < 4; ++nt) {
                psumP[warp * 32 + nt * 8 + 2 * tig]     = ps[nt][0];
                psumP[warp * 32 + nt * 8 + 2 * tig + 1] = ps[nt][1];
            }
        }
        __syncthreads();   // single barrier per block (parity buffer handles WAR)

        // every warp reduces its own rinv: lane L -> 1/denom of column s0+L
        float rv;
        {
            float tot = 0.f;
#pragma unroll
            for (int w = 0; w < 8; ++w) tot += psumP[w * 32 + lane];
            rv = 1.0f / tot;
        }

        if (anyact) {
            // PV in bf16 3-term, k16 (C-frag == A-frag layout, no P shuffles)
#pragma unroll
            for (int ch = 0; ch < 2; ++ch) {
                const int sb = s0 + ch * 16;
                unsigned pah[2][4], pal[2][4];
#pragma unroll
                for (int mt = 0; mt < 2; ++mt) {
                    if (mt == 0 && !act0) continue;
#pragma unroll
                    for (int hq = 0; hq < 2; ++hq) {
                        float e0 = ef[mt][2 * ch + hq][0];
                        float e1 = ef[mt][2 * ch + hq][1];
                        float e2 = ef[mt][2 * ch + hq][2];
                        float e3 = ef[mt][2 * ch + hq][3];
                        pah[mt][2 * hq]     = pk2(e0, e1);
                        pal[mt][2 * hq]     = pkres(e0, e1, pah[mt][2 * hq]);
                        pah[mt][2 * hq + 1] = pk2(e2, e3);
                        pal[mt][2 * hq + 1] = pkres(e2, e3, pah[mt][2 * hq + 1]);
                    }
                }
                float r0 = __shfl_sync(0xffffffffu, rv, ch * 16 + 2 * tig);
                float r1 = __shfl_sync(0xffffffffu, rv, ch * 16 + 2 * tig + 1);
                float r2 = __shfl_sync(0xffffffffu, rv, ch * 16 + 8 + 2 * tig);
                float r3 = __shfl_sync(0xffffffffu, rv, ch * 16 + 9 + 2 * tig);
#pragma unroll
                for (int nt = 0; nt < 2; ++nt) {
                    int d = nt * 8 + grp;
                    float b0 = v_s[(sb + 2 * tig)     * VPD + d] * r0;
                    float b1 = v_s[(sb + 2 * tig + 1) * VPD + d] * r1;
                    float b2 = v_s[(sb + 8 + 2 * tig) * VPD + d] * r2;
                    float b3 = v_s[(sb + 9 + 2 * tig) * VPD + d] * r3;
                    unsigned bh[2], bl[2];
                    bh[0] = pk2(b0, b1); bl[0] = pkres(b0, b1, bh[0]);
                    bh[1] = pk2(b2, b3); bl[1] = pkres(b2, b3, bh[1]);
                    if (act0) {
                        mma_bf16(oacc[0][nt], pah[0], bh);
                        mma_bf16(oacc[0][nt], pah[0], bl);
                        mma_bf16(oacc[0][nt], pal[0], bh);
                    }
                    mma_bf16(oacc[1][nt], pah[1], bh);
                    mma_bf16(oacc[1][nt], pah[1], bl);
                    mma_bf16(oacc[1][nt], pal[1], bh);
                }
            }
        }
    }

    float* ob = out + (size_t)b * TT * HSZ;
#pragma unroll
    for (int mt = 0; mt < 2; ++mt)
#pragma unroll
        for (int nt = 0; nt < 2; ++nt) {
            int r0 = rb[mt] + grp;
            int c  = nt * 8 + 2 * tig;
            *reinterpret_cast<float2*>(ob + r0 * HSZ + c) =
                make_float2(oacc[mt][nt][0], oacc[mt][nt][1]);
            *reinterpret_cast<float2*>(ob + (r0 + 8) * HSZ + c) =
                make_float2(oacc[mt][nt][2], oacc[mt][nt][3]);
        }
}

extern "C" void kernel_launch(void* const* d_in, const int* in_sizes, int n_in,
                              void* d_out, int out_size) {
    const float* x  = (const float*)d_in[0];
    const float* wk = (const float*)d_in[1];
    const float* wq = (const float*)d_in[2];
    const float* wv = (const float*)d_in[3];
    float* out      = (float*)d_out;

    const int B = in_sizes[0] / (TT * CC);  // 512

    cudaFuncSetAttribute(head_fused_kernel,
                         cudaFuncAttributeMaxDynamicSharedMemorySize, SMEM_BYTES);

    pack_w_kernel<<<18, 256>>>(wk, wq, wv);
    head_fused_kernel<<<B, 256, SMEM_BYTES>>>(x, out);
}